// round 1
// baseline (speedup 1.0000x reference)
#include <cuda_runtime.h>
#include <cuda_bf16.h>
#include <math.h>

// Problem constants
#define BATCH 2
#define SEQ   2048
#define CH    1024
#define NH    16
#define HD    64
#define C3    (3*CH)        // 3072
#define MROWS (BATCH*SEQ)   // 4096

// Scratch (allocation-guard safe: __device__ globals)
__device__ float g_qkv[(size_t)BATCH * SEQ * C3];   // [B,T,3C]
__device__ float g_y  [(size_t)BATCH * SEQ * CH];   // [B,T,C]

// ---------------------------------------------------------------------------
// GEMM: C[M,N] = A[M,K] @ B[K,N] + bias[N]    (all row-major fp32)
// BM=BN=64, BK=16, 256 threads, 4x4 register tile per thread.
// ---------------------------------------------------------------------------
__global__ __launch_bounds__(256, 4)
void gemm_bias_kernel(int M, int N, int K,
                      const float* __restrict__ A,
                      const float* __restrict__ B,
                      const float* __restrict__ bias,
                      float* __restrict__ C)
{
    __shared__ float As[16 * 68];   // transposed: As[k][m], stride 68
    __shared__ float Bs[16 * 64];   // Bs[k][n], stride 64

    const int tid = threadIdx.x;
    const int tx = tid & 15;        // col group 0..15
    const int ty = tid >> 4;        // row group 0..15
    const int n0 = blockIdx.x * 64;
    const int m0 = blockIdx.y * 64;

    float acc[4][4];
#pragma unroll
    for (int i = 0; i < 4; i++)
#pragma unroll
        for (int j = 0; j < 4; j++) acc[i][j] = 0.f;

    const int lm = tid >> 2;        // 0..63 : row for A load
    const int lk = (tid & 3) * 4;   // 0,4,8,12 : k group for A load
    const int bk_row = tid >> 4;    // 0..15 : k row for B load
    const int bk_col = (tid & 15) * 4;

    for (int kb = 0; kb < K; kb += 16) {
        // load A tile (64x16), store transposed As[k][m]
        float4 av = *(const float4*)(A + (size_t)(m0 + lm) * K + kb + lk);
        As[(lk + 0) * 68 + lm] = av.x;
        As[(lk + 1) * 68 + lm] = av.y;
        As[(lk + 2) * 68 + lm] = av.z;
        As[(lk + 3) * 68 + lm] = av.w;
        // load B tile (16x64)
        float4 bv = *(const float4*)(B + (size_t)(kb + bk_row) * N + n0 + bk_col);
        *(float4*)&Bs[bk_row * 64 + bk_col] = bv;
        __syncthreads();

#pragma unroll
        for (int k = 0; k < 16; k++) {
            float4 a4 = *(float4*)&As[k * 68 + ty * 4];
            float4 b4 = *(float4*)&Bs[k * 64 + tx * 4];
            float ar[4] = {a4.x, a4.y, a4.z, a4.w};
            float br[4] = {b4.x, b4.y, b4.z, b4.w};
#pragma unroll
            for (int i = 0; i < 4; i++)
#pragma unroll
                for (int j = 0; j < 4; j++)
                    acc[i][j] += ar[i] * br[j];
        }
        __syncthreads();
    }

    float4 bb = *(const float4*)(bias + n0 + tx * 4);
    float biasr[4] = {bb.x, bb.y, bb.z, bb.w};
#pragma unroll
    for (int i = 0; i < 4; i++) {
        float4 o;
        o.x = acc[i][0] + biasr[0];
        o.y = acc[i][1] + biasr[1];
        o.z = acc[i][2] + biasr[2];
        o.w = acc[i][3] + biasr[3];
        *(float4*)(C + (size_t)(m0 + ty * 4 + i) * N + n0 + tx * 4) = o;
    }
}

// ---------------------------------------------------------------------------
// Flash attention (fp32, causal). One CTA per (64-query tile, head, batch).
// 256 threads: ty=tid/16 -> 4 rows (ty*4..), tx=tid%16 -> 4 cols (tx*4..).
// Online softmax state per row duplicated across the 16 lanes sharing it.
// Dyn smem: Qs[64][64] + Ks[64][68] + Vs[64][68] + Ss[64][68]  = 68608 B
// ---------------------------------------------------------------------------
#define QS_STRIDE 64
#define KS_STRIDE 68
#define FLASH_SMEM ((64*64 + 3*64*68) * 4)

__global__ __launch_bounds__(256, 1)
void flash_attn_kernel(const float* __restrict__ qkv, float* __restrict__ y)
{
    extern __shared__ float sm[];
    float* Qs = sm;                    // 64*64
    float* Ks = Qs + 64 * 64;          // 64*68
    float* Vs = Ks + 64 * 68;          // 64*68
    float* Ss = Vs + 64 * 68;          // 64*68

    const int tid = threadIdx.x;
    const int tx = tid & 15;
    const int ty = tid >> 4;
    const int qt = blockIdx.x;     // query tile 0..31
    const int h  = blockIdx.y;     // head
    const int b  = blockIdx.z;     // batch

    const int q0 = qt * 64;
    const float* qb = qkv + ((size_t)(b * SEQ + q0)) * C3 + h * HD;          // Q rows
    const float* kb = qkv + ((size_t)(b * SEQ)) * C3 + CH + h * HD;          // K base
    const float* vb = kb + CH;                                               // V base

    // load Q tile, pre-scaled by 1/sqrt(HD)
    const float scale = 0.125f;
    for (int i = tid; i < 64 * 16; i += 256) {
        int row = i >> 4, c4 = (i & 15) * 4;
        float4 v = *(const float4*)(qb + (size_t)row * C3 + c4);
        float* d = &Qs[row * QS_STRIDE + c4];
        d[0] = v.x * scale; d[1] = v.y * scale; d[2] = v.z * scale; d[3] = v.w * scale;
    }

    float m[4], l[4], acc[4][4];
#pragma unroll
    for (int i = 0; i < 4; i++) {
        m[i] = -1e30f; l[i] = 0.f;
#pragma unroll
        for (int j = 0; j < 4; j++) acc[i][j] = 0.f;
    }
    __syncthreads();

    for (int kt = 0; kt <= qt; kt++) {
        if (kt > 0) __syncthreads();   // prior PV reads of Vs must finish
        // load K,V tiles
        for (int i = tid; i < 64 * 16; i += 256) {
            int row = i >> 4, c4 = (i & 15) * 4;
            size_t g = (size_t)(kt * 64 + row) * C3 + c4;
            *(float4*)&Ks[row * KS_STRIDE + c4] = *(const float4*)(kb + g);
            *(float4*)&Vs[row * KS_STRIDE + c4] = *(const float4*)(vb + g);
        }
        __syncthreads();

        // S = Q K^T  (rows 4ty.., cols 4tx..)
        float s[4][4];
#pragma unroll
        for (int i = 0; i < 4; i++)
#pragma unroll
            for (int j = 0; j < 4; j++) s[i][j] = 0.f;

#pragma unroll
        for (int d4 = 0; d4 < 16; d4++) {
            float4 qv[4], kv[4];
#pragma unroll
            for (int i = 0; i < 4; i++)
                qv[i] = *(float4*)&Qs[(ty * 4 + i) * QS_STRIDE + d4 * 4];
#pragma unroll
            for (int j = 0; j < 4; j++)
                kv[j] = *(float4*)&Ks[(tx * 4 + j) * KS_STRIDE + d4 * 4];
#pragma unroll
            for (int i = 0; i < 4; i++)
#pragma unroll
                for (int j = 0; j < 4; j++)
                    s[i][j] += qv[i].x * kv[j].x + qv[i].y * kv[j].y
                             + qv[i].z * kv[j].z + qv[i].w * kv[j].w;
        }

        // causal mask on diagonal tile
        if (kt == qt) {
#pragma unroll
            for (int i = 0; i < 4; i++)
#pragma unroll
                for (int j = 0; j < 4; j++)
                    if (tx * 4 + j > ty * 4 + i) s[i][j] = -1e30f;
        }

        // row max (reduce over 16 lanes sharing the row)
        float rmax[4];
#pragma unroll
        for (int i = 0; i < 4; i++) {
            float v = fmaxf(fmaxf(s[i][0], s[i][1]), fmaxf(s[i][2], s[i][3]));
            v = fmaxf(v, __shfl_xor_sync(0xffffffffu, v, 1));
            v = fmaxf(v, __shfl_xor_sync(0xffffffffu, v, 2));
            v = fmaxf(v, __shfl_xor_sync(0xffffffffu, v, 4));
            v = fmaxf(v, __shfl_xor_sync(0xffffffffu, v, 8));
            rmax[i] = v;
        }

        float fac[4], rsum[4];
        float p[4][4];
#pragma unroll
        for (int i = 0; i < 4; i++) {
            float mn = fmaxf(m[i], rmax[i]);
            fac[i] = __expf(m[i] - mn);
            m[i] = mn;
            float rs = 0.f;
#pragma unroll
            for (int j = 0; j < 4; j++) {
                p[i][j] = __expf(s[i][j] - mn);
                rs += p[i][j];
            }
            rs += __shfl_xor_sync(0xffffffffu, rs, 1);
            rs += __shfl_xor_sync(0xffffffffu, rs, 2);
            rs += __shfl_xor_sync(0xffffffffu, rs, 4);
            rs += __shfl_xor_sync(0xffffffffu, rs, 8);
            rsum[i] = rs;
        }
#pragma unroll
        for (int i = 0; i < 4; i++) {
            l[i] = l[i] * fac[i] + rsum[i];
#pragma unroll
            for (int j = 0; j < 4; j++) acc[i][j] *= fac[i];
        }

        // stage P in smem
#pragma unroll
        for (int i = 0; i < 4; i++) {
            float4 o = {p[i][0], p[i][1], p[i][2], p[i][3]};
            *(float4*)&Ss[(ty * 4 + i) * KS_STRIDE + tx * 4] = o;
        }
        __syncthreads();

        // acc += P @ V
#pragma unroll
        for (int j4 = 0; j4 < 16; j4++) {
            float4 pv[4], vv[4];
#pragma unroll
            for (int i = 0; i < 4; i++)
                pv[i] = *(float4*)&Ss[(ty * 4 + i) * KS_STRIDE + j4 * 4];
#pragma unroll
            for (int jj = 0; jj < 4; jj++)
                vv[jj] = *(float4*)&Vs[(j4 * 4 + jj) * KS_STRIDE + tx * 4];
#pragma unroll
            for (int i = 0; i < 4; i++) {
                acc[i][0] += pv[i].x * vv[0].x + pv[i].y * vv[1].x + pv[i].z * vv[2].x + pv[i].w * vv[3].x;
                acc[i][1] += pv[i].x * vv[0].y + pv[i].y * vv[1].y + pv[i].z * vv[2].y + pv[i].w * vv[3].y;
                acc[i][2] += pv[i].x * vv[0].z + pv[i].y * vv[1].z + pv[i].z * vv[2].z + pv[i].w * vv[3].z;
                acc[i][3] += pv[i].x * vv[0].w + pv[i].y * vv[1].w + pv[i].z * vv[2].w + pv[i].w * vv[3].w;
            }
        }
    }

    // epilogue: y[b, q0+row, h*64 + col] = acc / l
    float* yb = y + ((size_t)(b * SEQ + q0)) * CH + h * HD;
#pragma unroll
    for (int i = 0; i < 4; i++) {
        float inv = 1.f / l[i];
        float4 o = {acc[i][0] * inv, acc[i][1] * inv, acc[i][2] * inv, acc[i][3] * inv};
        *(float4*)(yb + (size_t)(ty * 4 + i) * CH + tx * 4) = o;
    }
}

// ---------------------------------------------------------------------------
extern "C" void kernel_launch(void* const* d_in, const int* in_sizes, int n_in,
                              void* d_out, int out_size)
{
    const float* x     = (const float*)d_in[0];
    const float* w_qkv = (const float*)d_in[1];
    const float* b_qkv = (const float*)d_in[2];
    const float* w_out = (const float*)d_in[3];
    const float* b_out = (const float*)d_in[4];
    float* out = (float*)d_out;

    float* qkv; cudaGetSymbolAddress((void**)&qkv, g_qkv);
    float* y;   cudaGetSymbolAddress((void**)&y,   g_y);

    static bool attr_set = false;
    if (!attr_set) {
        cudaFuncSetAttribute(flash_attn_kernel,
                             cudaFuncAttributeMaxDynamicSharedMemorySize, FLASH_SMEM);
        attr_set = true;
    }

    // 1) QKV projection: [4096,1024] @ [1024,3072] + b
    {
        dim3 grid(C3 / 64, MROWS / 64);
        gemm_bias_kernel<<<grid, 256>>>(MROWS, C3, CH, x, w_qkv, b_qkv, qkv);
    }
    // 2) causal flash attention -> y [B,T,C]
    {
        dim3 grid(SEQ / 64, NH, BATCH);
        flash_attn_kernel<<<grid, 256, FLASH_SMEM>>>(qkv, y);
    }
    // 3) output projection: [4096,1024] @ [1024,1024] + b
    {
        dim3 grid(CH / 64, MROWS / 64);
        gemm_bias_kernel<<<grid, 256>>>(MROWS, CH, CH, y, w_out, b_out, out);
    }
}

// round 3
// speedup vs baseline: 3.8657x; 3.8657x over previous
#include <cuda_runtime.h>
#include <cuda_bf16.h>
#include <cstdint>
#include <math.h>

// Problem constants
#define BATCH 2
#define SEQ   2048
#define CH    1024
#define NH    16
#define HD    64
#define C3    (3*CH)        // 3072
#define MROWS (BATCH*SEQ)   // 4096

// Scratch (allocation-guard safe: __device__ globals)
__device__ float g_qkv[(size_t)BATCH * SEQ * C3];   // [B,T,3C] fp32 gemm output
__device__ float g_y  [(size_t)BATCH * SEQ * CH];   // [B,T,C]  attention out (tf32-rounded)
__device__ float g_xr [(size_t)BATCH * SEQ * CH];   // x, tf32-rounded
__device__ float g_wtq[(size_t)C3 * CH];            // w_qkv^T [3C, C], tf32-rounded
__device__ float g_wto[(size_t)CH * CH];            // w_out^T [C, C], tf32-rounded

// ---------------------------------------------------------------------------
// Helpers
// ---------------------------------------------------------------------------
__device__ __forceinline__ float to_tf32(float x) {
    float r; asm("cvt.rna.tf32.f32 %0, %1;" : "=f"(r) : "f"(x)); return r;
}
__device__ __forceinline__ uint32_t fbits(float x) { return __float_as_uint(x); }

__device__ __forceinline__ uint32_t smem_u32(const void* p) {
    uint32_t a;
    asm("{ .reg .u64 t; cvta.to.shared.u64 t, %1; cvt.u32.u64 %0, t; }" : "=r"(a) : "l"(p));
    return a;
}
__device__ __forceinline__ void cp16(uint32_t s, const void* g) {
    asm volatile("cp.async.cg.shared.global [%0], [%1], 16;" :: "r"(s), "l"(g));
}

// m16n8k8 tf32 MMA, D += A*B (C=D accumulate in place)
__device__ __forceinline__ void mma_tf32(float* d,
                                         uint32_t a0, uint32_t a1, uint32_t a2, uint32_t a3,
                                         uint32_t b0, uint32_t b1) {
    asm volatile(
        "mma.sync.aligned.m16n8k8.row.col.f32.tf32.tf32.f32 "
        "{%0,%1,%2,%3}, {%4,%5,%6,%7}, {%8,%9}, {%0,%1,%2,%3};"
        : "+f"(d[0]), "+f"(d[1]), "+f"(d[2]), "+f"(d[3])
        : "r"(a0), "r"(a1), "r"(a2), "r"(a3), "r"(b0), "r"(b1));
}

// ---------------------------------------------------------------------------
// Elementwise tf32 round (for x)
// ---------------------------------------------------------------------------
__global__ __launch_bounds__(256)
void round_tf32_kernel(const float* __restrict__ in, float* __restrict__ out)
{
    int i = (blockIdx.x * 256 + threadIdx.x) * 4;
    float4 v = *(const float4*)(in + i);
    v.x = to_tf32(v.x); v.y = to_tf32(v.y); v.z = to_tf32(v.z); v.w = to_tf32(v.w);
    *(float4*)(out + i) = v;
}

// ---------------------------------------------------------------------------
// Transpose + tf32-round: out[c][r] = tf32(in[r][c]), in is [R,C]
// ---------------------------------------------------------------------------
__global__ __launch_bounds__(256, 8)
void transpose_round_kernel(const float* __restrict__ in, float* __restrict__ out, int R, int C)
{
    __shared__ float t[32][33];
    int tx = threadIdx.x, ty = threadIdx.y;     // 32 x 8
    int c0 = blockIdx.x * 32, r0 = blockIdx.y * 32;
#pragma unroll
    for (int k = 0; k < 4; k++)
        t[ty + 8 * k][tx] = in[(size_t)(r0 + ty + 8 * k) * C + c0 + tx];
    __syncthreads();
#pragma unroll
    for (int k = 0; k < 4; k++)
        out[(size_t)(c0 + ty + 8 * k) * R + r0 + tx] = to_tf32(t[tx][ty + 8 * k]);
}

// ---------------------------------------------------------------------------
// TF32 mma.sync GEMM: C[M,N] = A[M,K] @ Bt[N,K]^T + bias[N]
// A, Bt pre-rounded to tf32. CTA 128x128, KC=32, cp.async double-buffered.
// 256 threads = 8 warps in 2(m) x 4(n); warp tile 64x32.
// smem stride 36 floats -> conflict-free fragment quads ((36r+c)%32 = 4r+c).
// ---------------------------------------------------------------------------
#define GKC 32
#define GSTR 36
#define GTILE (128 * GSTR)                   // floats per buffer
#define G_SMEM (4 * GTILE * 4)               // A0,A1,B0,B1  = 73728 B

__global__ __launch_bounds__(256, 2)
void gemm_mma_kernel(int M, int N, int K,
                     const float* __restrict__ A,
                     const float* __restrict__ Bt,
                     const float* __restrict__ bias,
                     float* __restrict__ C)
{
    extern __shared__ float smg[];
    const uint32_t smem_base = smem_u32(smg);

    const int tid = threadIdx.x;
    const int lane = tid & 31, wid = tid >> 5;
    const int n0 = blockIdx.x * 128;
    const int m0 = blockIdx.y * 128;
    const int mb = (wid & 1) * 64;
    const int nb = (wid >> 1) * 32;

    float acc[4][4][4];
#pragma unroll
    for (int mt = 0; mt < 4; mt++)
#pragma unroll
        for (int nt = 0; nt < 4; nt++)
#pragma unroll
            for (int r = 0; r < 4; r++) acc[mt][nt][r] = 0.f;

    const int lr = tid >> 3;            // 0..31 : row block per p
    const int lc4 = (tid & 7) * 4;      // 0..28 : col group

    const int nch = K / GKC;

    // issue loads for chunk into buffer buf
    auto issue = [&](int buf, int kb) {
        uint32_t a_s = smem_base + (uint32_t)buf * GTILE * 4;
        uint32_t b_s = smem_base + (uint32_t)(2 + buf) * GTILE * 4;
#pragma unroll
        for (int p = 0; p < 4; p++) {
            int r = lr + p * 32;
            cp16(a_s + (uint32_t)(r * GSTR + lc4) * 4, A  + (size_t)(m0 + r) * K + kb + lc4);
            cp16(b_s + (uint32_t)(r * GSTR + lc4) * 4, Bt + (size_t)(n0 + r) * K + kb + lc4);
        }
        asm volatile("cp.async.commit_group;");
    };

    issue(0, 0);
    for (int c = 0; c < nch; c++) {
        if (c + 1 < nch) {
            issue((c + 1) & 1, (c + 1) * GKC);
            asm volatile("cp.async.wait_group 1;");
        } else {
            asm volatile("cp.async.wait_group 0;");
        }
        __syncthreads();

        const float* Ab = smg + (c & 1) * GTILE;
        const float* Bb = smg + (2 + (c & 1)) * GTILE;
#pragma unroll
        for (int k = 0; k < 4; k++) {
            const int kk = k * 8;
            uint32_t af[4][4];
#pragma unroll
            for (int mt = 0; mt < 4; mt++) {
                const float* pa = Ab + (mb + mt * 16 + (lane >> 2)) * GSTR + kk + (lane & 3);
                af[mt][0] = fbits(pa[0]);
                af[mt][1] = fbits(pa[8 * GSTR]);
                af[mt][2] = fbits(pa[4]);
                af[mt][3] = fbits(pa[8 * GSTR + 4]);
            }
#pragma unroll
            for (int nt = 0; nt < 4; nt++) {
                const float* pb = Bb + (nb + nt * 8 + (lane >> 2)) * GSTR + kk + (lane & 3);
                uint32_t b0 = fbits(pb[0]), b1 = fbits(pb[4]);
#pragma unroll
                for (int mt = 0; mt < 4; mt++)
                    mma_tf32(acc[mt][nt], af[mt][0], af[mt][1], af[mt][2], af[mt][3], b0, b1);
            }
        }
        __syncthreads();
    }

    // epilogue
#pragma unroll
    for (int mt = 0; mt < 4; mt++) {
        const int row0 = m0 + mb + mt * 16 + (lane >> 2);
#pragma unroll
        for (int nt = 0; nt < 4; nt++) {
            const int col = n0 + nb + nt * 8 + (lane & 3) * 2;
            float bv0 = __ldg(bias + col), bv1 = __ldg(bias + col + 1);
            float2 o0 = { acc[mt][nt][0] + bv0, acc[mt][nt][1] + bv1 };
            float2 o1 = { acc[mt][nt][2] + bv0, acc[mt][nt][3] + bv1 };
            *(float2*)(C + (size_t)row0 * N + col)       = o0;
            *(float2*)(C + (size_t)(row0 + 8) * N + col) = o1;
        }
    }
}

// ---------------------------------------------------------------------------
// Flash attention, tf32 mma.sync, causal.
// CTA = 64 q-rows x (head, batch); 128 threads = 4 warps, warp owns 16 rows.
// smem: Qs/Ks/Ps stride 68, Vs stride 72 (conflict-free B-frags for PV).
// ---------------------------------------------------------------------------
#define FSTR 68
#define VSTR 72
#define OFF_Q 0
#define OFF_K (64 * FSTR)
#define OFF_V (2 * 64 * FSTR)
#define OFF_P (2 * 64 * FSTR + 64 * VSTR)
#define FLASH_SMEM ((3 * 64 * FSTR + 64 * VSTR) * 4)   // 70656 B

__global__ __launch_bounds__(128, 3)
void flash_mma_kernel(const float* __restrict__ qkv, float* __restrict__ y)
{
    extern __shared__ float smf[];
    float* Qs = smf + OFF_Q;
    float* Ks = smf + OFF_K;
    float* Vs = smf + OFF_V;
    float* Ps = smf + OFF_P;

    const int tid = threadIdx.x;
    const int lane = tid & 31, wid = tid >> 5;
    const int qt = blockIdx.x;
    const int h  = blockIdx.y;
    const int b  = blockIdx.z;
    const int q0 = qt * 64;

    const float* qb = qkv + ((size_t)(b * SEQ + q0)) * C3 + h * HD;
    const float* kb = qkv + ((size_t)(b * SEQ)) * C3 + CH + h * HD;
    const float* vb = kb + CH;

    // Q: scale + tf32 round into smem
    const float scale = 0.125f;
    for (int i = tid; i < 64 * 16; i += 128) {
        int row = i >> 4, c4 = (i & 15) * 4;
        float4 v = *(const float4*)(qb + (size_t)row * C3 + c4);
        float4 o;
        o.x = to_tf32(v.x * scale); o.y = to_tf32(v.y * scale);
        o.z = to_tf32(v.z * scale); o.w = to_tf32(v.w * scale);
        *(float4*)&Qs[row * FSTR + c4] = o;
    }
    __syncthreads();

    float m0r = -1e30f, m1r = -1e30f, l0 = 0.f, l1 = 0.f;
    float oacc[8][4];
#pragma unroll
    for (int nt = 0; nt < 8; nt++)
#pragma unroll
        for (int r = 0; r < 4; r++) oacc[nt][r] = 0.f;

    const int qrow = 16 * wid + (lane >> 2);    // local q row (first half)

    for (int kt = 0; kt <= qt; kt++) {
        // load K,V tile (tf32-rounded)
        for (int i = tid; i < 64 * 16; i += 128) {
            int row = i >> 4, c4 = (i & 15) * 4;
            size_t g = (size_t)(kt * 64 + row) * C3 + c4;
            float4 kv = *(const float4*)(kb + g);
            float4 vv = *(const float4*)(vb + g);
            float4 ko, vo;
            ko.x = to_tf32(kv.x); ko.y = to_tf32(kv.y); ko.z = to_tf32(kv.z); ko.w = to_tf32(kv.w);
            vo.x = to_tf32(vv.x); vo.y = to_tf32(vv.y); vo.z = to_tf32(vv.z); vo.w = to_tf32(vv.w);
            *(float4*)&Ks[row * FSTR + c4] = ko;
            *(float4*)&Vs[row * VSTR + c4] = vo;
        }
        __syncthreads();

        // S = Q @ K^T   (warp: 16 x 64)
        float sacc[8][4];
#pragma unroll
        for (int nt = 0; nt < 8; nt++)
#pragma unroll
            for (int r = 0; r < 4; r++) sacc[nt][r] = 0.f;

#pragma unroll
        for (int k = 0; k < 8; k++) {
            const int kk = k * 8;
            const float* pa = &Qs[qrow * FSTR + kk + (lane & 3)];
            uint32_t a0 = fbits(pa[0]), a1 = fbits(pa[8 * FSTR]);
            uint32_t a2 = fbits(pa[4]), a3 = fbits(pa[8 * FSTR + 4]);
#pragma unroll
            for (int nt = 0; nt < 8; nt++) {
                const float* pb = &Ks[(nt * 8 + (lane >> 2)) * FSTR + kk + (lane & 3)];
                mma_tf32(sacc[nt], a0, a1, a2, a3, fbits(pb[0]), fbits(pb[4]));
            }
        }

        // causal mask on diagonal tile
        if (kt == qt) {
#pragma unroll
            for (int nt = 0; nt < 8; nt++) {
                int c0 = nt * 8 + (lane & 3) * 2;
                if (c0     > qrow)     sacc[nt][0] = -1e30f;
                if (c0 + 1 > qrow)     sacc[nt][1] = -1e30f;
                if (c0     > qrow + 8) sacc[nt][2] = -1e30f;
                if (c0 + 1 > qrow + 8) sacc[nt][3] = -1e30f;
            }
        }

        // online softmax (two row-halves per thread)
        float mx0 = -1e30f, mx1 = -1e30f;
#pragma unroll
        for (int nt = 0; nt < 8; nt++) {
            mx0 = fmaxf(mx0, fmaxf(sacc[nt][0], sacc[nt][1]));
            mx1 = fmaxf(mx1, fmaxf(sacc[nt][2], sacc[nt][3]));
        }
        mx0 = fmaxf(mx0, __shfl_xor_sync(0xffffffffu, mx0, 1));
        mx0 = fmaxf(mx0, __shfl_xor_sync(0xffffffffu, mx0, 2));
        mx1 = fmaxf(mx1, __shfl_xor_sync(0xffffffffu, mx1, 1));
        mx1 = fmaxf(mx1, __shfl_xor_sync(0xffffffffu, mx1, 2));

        float mn0 = fmaxf(m0r, mx0), mn1 = fmaxf(m1r, mx1);
        float fac0 = __expf(m0r - mn0), fac1 = __expf(m1r - mn1);
        m0r = mn0; m1r = mn1;

        float rs0 = 0.f, rs1 = 0.f;
#pragma unroll
        for (int nt = 0; nt < 8; nt++) {
            sacc[nt][0] = __expf(sacc[nt][0] - mn0);
            sacc[nt][1] = __expf(sacc[nt][1] - mn0);
            sacc[nt][2] = __expf(sacc[nt][2] - mn1);
            sacc[nt][3] = __expf(sacc[nt][3] - mn1);
            rs0 += sacc[nt][0] + sacc[nt][1];
            rs1 += sacc[nt][2] + sacc[nt][3];
        }
        rs0 += __shfl_xor_sync(0xffffffffu, rs0, 1);
        rs0 += __shfl_xor_sync(0xffffffffu, rs0, 2);
        rs1 += __shfl_xor_sync(0xffffffffu, rs1, 1);
        rs1 += __shfl_xor_sync(0xffffffffu, rs1, 2);

        l0 = l0 * fac0 + rs0;
        l1 = l1 * fac1 + rs1;
#pragma unroll
        for (int nt = 0; nt < 8; nt++) {
            oacc[nt][0] *= fac0; oacc[nt][1] *= fac0;
            oacc[nt][2] *= fac1; oacc[nt][3] *= fac1;
        }

        // stage P (tf32-rounded) — warp-private rows
#pragma unroll
        for (int nt = 0; nt < 8; nt++) {
            int c = nt * 8 + (lane & 3) * 2;
            float2 p0 = { to_tf32(sacc[nt][0]), to_tf32(sacc[nt][1]) };
            float2 p1 = { to_tf32(sacc[nt][2]), to_tf32(sacc[nt][3]) };
            *(float2*)&Ps[qrow * FSTR + c]       = p0;
            *(float2*)&Ps[(qrow + 8) * FSTR + c] = p1;
        }
        __syncwarp();

        // O += P @ V   (warp: 16 x 64, k = 64 keys)
#pragma unroll
        for (int k = 0; k < 8; k++) {
            const int kk = k * 8;
            const float* pa = &Ps[qrow * FSTR + kk + (lane & 3)];
            uint32_t a0 = fbits(pa[0]), a1 = fbits(pa[8 * FSTR]);
            uint32_t a2 = fbits(pa[4]), a3 = fbits(pa[8 * FSTR + 4]);
#pragma unroll
            for (int nt = 0; nt < 8; nt++) {
                uint32_t b0 = fbits(Vs[(kk +     (lane & 3)) * VSTR + nt * 8 + (lane >> 2)]);
                uint32_t b1 = fbits(Vs[(kk + 4 + (lane & 3)) * VSTR + nt * 8 + (lane >> 2)]);
                mma_tf32(oacc[nt], a0, a1, a2, a3, b0, b1);
            }
        }
        __syncthreads();   // before next K/V overwrite
    }

    // epilogue: divide by l, tf32-round (input to out-proj), store
    float inv0 = 1.f / l0, inv1 = 1.f / l1;
    int r0 = q0 + 16 * wid + (lane >> 2);
    float* y0 = y + ((size_t)(b * SEQ + r0)) * CH + h * HD;
    float* y1 = y0 + 8 * CH;
#pragma unroll
    for (int nt = 0; nt < 8; nt++) {
        int c = nt * 8 + (lane & 3) * 2;
        float2 o0 = { to_tf32(oacc[nt][0] * inv0), to_tf32(oacc[nt][1] * inv0) };
        float2 o1 = { to_tf32(oacc[nt][2] * inv1), to_tf32(oacc[nt][3] * inv1) };
        *(float2*)(y0 + c) = o0;
        *(float2*)(y1 + c) = o1;
    }
}

// ---------------------------------------------------------------------------
extern "C" void kernel_launch(void* const* d_in, const int* in_sizes, int n_in,
                              void* d_out, int out_size)
{
    const float* x     = (const float*)d_in[0];
    const float* w_qkv = (const float*)d_in[1];
    const float* b_qkv = (const float*)d_in[2];
    const float* w_out = (const float*)d_in[3];
    const float* b_out = (const float*)d_in[4];
    float* out = (float*)d_out;

    float* qkv; cudaGetSymbolAddress((void**)&qkv, g_qkv);
    float* y;   cudaGetSymbolAddress((void**)&y,   g_y);
    float* xr;  cudaGetSymbolAddress((void**)&xr,  g_xr);
    float* wtq; cudaGetSymbolAddress((void**)&wtq, g_wtq);
    float* wto; cudaGetSymbolAddress((void**)&wto, g_wto);

    static bool attr_set = false;
    if (!attr_set) {
        cudaFuncSetAttribute(gemm_mma_kernel,
                             cudaFuncAttributeMaxDynamicSharedMemorySize, G_SMEM);
        cudaFuncSetAttribute(flash_mma_kernel,
                             cudaFuncAttributeMaxDynamicSharedMemorySize, FLASH_SMEM);
        attr_set = true;
    }

    // 0) precondition operands to tf32
    round_tf32_kernel<<<(MROWS * CH) / (256 * 4), 256>>>(x, xr);
    {
        dim3 blk(32, 8);
        transpose_round_kernel<<<dim3(C3 / 32, CH / 32), blk>>>(w_qkv, wtq, CH, C3);
        transpose_round_kernel<<<dim3(CH / 32, CH / 32), blk>>>(w_out, wto, CH, CH);
    }
    // 1) QKV projection: [4096,1024] @ [1024,3072] + b
    {
        dim3 grid(C3 / 128, MROWS / 128);
        gemm_mma_kernel<<<grid, 256, G_SMEM>>>(MROWS, C3, CH, xr, wtq, b_qkv, qkv);
    }
    // 2) causal flash attention -> y (tf32-rounded)
    {
        dim3 grid(SEQ / 64, NH, BATCH);
        flash_mma_kernel<<<grid, 128, FLASH_SMEM>>>(qkv, y);
    }
    // 3) output projection: [4096,1024] @ [1024,1024] + b
    {
        dim3 grid(CH / 128, MROWS / 128);
        gemm_mma_kernel<<<grid, 256, G_SMEM>>>(MROWS, CH, CH, y, wto, b_out, out);
    }
}

// round 5
// speedup vs baseline: 3.8695x; 1.0010x over previous
#include <cuda_runtime.h>
#include <cuda_bf16.h>
#include <cstdint>
#include <math.h>

// Problem constants
#define BATCH 2
#define SEQ   2048
#define CH    1024
#define NH    16
#define HD    64
#define C3    (3*CH)        // 3072
#define MROWS (BATCH*SEQ)   // 4096

// Scratch (allocation-guard safe: __device__ globals)
__device__ float g_qkv[(size_t)BATCH * SEQ * C3];   // [B,T,3C] fp32 gemm output
__device__ float g_y  [(size_t)BATCH * SEQ * CH];   // [B,T,C]  attention out (tf32-rounded)
__device__ float g_xr [(size_t)BATCH * SEQ * CH];   // x, tf32-rounded
__device__ float g_wtq[(size_t)C3 * CH];            // w_qkv^T [3C, C], tf32-rounded
__device__ float g_wto[(size_t)CH * CH];            // w_out^T [C, C], tf32-rounded

// ---------------------------------------------------------------------------
// Helpers
// ---------------------------------------------------------------------------
__device__ __forceinline__ float to_tf32(float x) {
    float r; asm("cvt.rna.tf32.f32 %0, %1;" : "=f"(r) : "f"(x)); return r;
}
__device__ __forceinline__ uint32_t fbits(float x) { return __float_as_uint(x); }

__device__ __forceinline__ uint32_t smem_u32(const void* p) {
    uint32_t a;
    asm("{ .reg .u64 t; cvta.to.shared.u64 t, %1; cvt.u32.u64 %0, t; }" : "=r"(a) : "l"(p));
    return a;
}
__device__ __forceinline__ void cp16(uint32_t s, const void* g) {
    asm volatile("cp.async.cg.shared.global [%0], [%1], 16;" :: "r"(s), "l"(g));
}

// m16n8k8 tf32 MMA, D += A*B
__device__ __forceinline__ void mma_tf32(float* d,
                                         uint32_t a0, uint32_t a1, uint32_t a2, uint32_t a3,
                                         uint32_t b0, uint32_t b1) {
    asm volatile(
        "mma.sync.aligned.m16n8k8.row.col.f32.tf32.tf32.f32 "
        "{%0,%1,%2,%3}, {%4,%5,%6,%7}, {%8,%9}, {%0,%1,%2,%3};"
        : "+f"(d[0]), "+f"(d[1]), "+f"(d[2]), "+f"(d[3])
        : "r"(a0), "r"(a1), "r"(a2), "r"(a3), "r"(b0), "r"(b1));
}

// ---------------------------------------------------------------------------
// Elementwise tf32 round (for x)
// ---------------------------------------------------------------------------
__global__ __launch_bounds__(256)
void round_tf32_kernel(const float* __restrict__ in, float* __restrict__ out)
{
    int i = (blockIdx.x * 256 + threadIdx.x) * 4;
    float4 v = *(const float4*)(in + i);
    v.x = to_tf32(v.x); v.y = to_tf32(v.y); v.z = to_tf32(v.z); v.w = to_tf32(v.w);
    *(float4*)(out + i) = v;
}

// ---------------------------------------------------------------------------
// Transpose + tf32-round: out[c][r] = tf32(in[r][c]), in is [R,C]
// ---------------------------------------------------------------------------
__global__ __launch_bounds__(256, 8)
void transpose_round_kernel(const float* __restrict__ in, float* __restrict__ out, int R, int C)
{
    __shared__ float t[32][33];
    int tx = threadIdx.x, ty = threadIdx.y;     // 32 x 8
    int c0 = blockIdx.x * 32, r0 = blockIdx.y * 32;
#pragma unroll
    for (int k = 0; k < 4; k++)
        t[ty + 8 * k][tx] = in[(size_t)(r0 + ty + 8 * k) * C + c0 + tx];
    __syncthreads();
#pragma unroll
    for (int k = 0; k < 4; k++)
        out[(size_t)(c0 + ty + 8 * k) * R + r0 + tx] = to_tf32(t[tx][ty + 8 * k]);
}

// ---------------------------------------------------------------------------
// TF32 mma.sync GEMM: C[M,N] = A[M,K] @ Bt[N,K]^T + bias[N]
// CTA 128x128, KC=32, 3-stage cp.async pipeline, one sync per chunk.
// 256 threads = 8 warps in 2(m) x 4(n); warp tile 64x32.
// smem stride 36 floats -> conflict-free fragment quads.
// ---------------------------------------------------------------------------
#define GKC 32
#define GSTR 36
#define GTILE (128 * GSTR)                   // floats per buffer (18432 B)
#define GSTAGES 3
#define G_SMEM (2 * GSTAGES * GTILE * 4)     // 110592 B

__global__ __launch_bounds__(256, 2)
void gemm_mma_kernel(int M, int N, int K,
                     const float* __restrict__ A,
                     const float* __restrict__ Bt,
                     const float* __restrict__ bias,
                     float* __restrict__ C)
{
    extern __shared__ float smg[];
    const uint32_t smem_base = smem_u32(smg);

    const int tid = threadIdx.x;
    const int lane = tid & 31, wid = tid >> 5;
    const int n0 = blockIdx.x * 128;
    const int m0 = blockIdx.y * 128;
    const int mb = (wid & 1) * 64;
    const int nb = (wid >> 1) * 32;

    float acc[4][4][4];
#pragma unroll
    for (int mt = 0; mt < 4; mt++)
#pragma unroll
        for (int nt = 0; nt < 4; nt++)
#pragma unroll
            for (int r = 0; r < 4; r++) acc[mt][nt][r] = 0.f;

    const int lr = tid >> 3;            // 0..31 : row block per p
    const int lc4 = (tid & 7) * 4;      // 0..28 : col group

    const int nch = K / GKC;

    auto issue = [&](int buf, int kb) {
        uint32_t a_s = smem_base + (uint32_t)buf * GTILE * 4;
        uint32_t b_s = smem_base + (uint32_t)(GSTAGES + buf) * GTILE * 4;
#pragma unroll
        for (int p = 0; p < 4; p++) {
            int r = lr + p * 32;
            cp16(a_s + (uint32_t)(r * GSTR + lc4) * 4, A  + (size_t)(m0 + r) * K + kb + lc4);
            cp16(b_s + (uint32_t)(r * GSTR + lc4) * 4, Bt + (size_t)(n0 + r) * K + kb + lc4);
        }
        asm volatile("cp.async.commit_group;");
    };

    issue(0, 0);
    if (nch > 1) issue(1, GKC);

    for (int c = 0; c < nch; c++) {
        if (c + 1 < nch) asm volatile("cp.async.wait_group 1;");
        else             asm volatile("cp.async.wait_group 0;");
        __syncthreads();
        if (c + 2 < nch) issue((c + 2) % GSTAGES, (c + 2) * GKC);

        const float* Ab = smg + (c % GSTAGES) * GTILE;
        const float* Bb = smg + (GSTAGES + (c % GSTAGES)) * GTILE;
#pragma unroll
        for (int k = 0; k < 4; k++) {
            const int kk = k * 8;
            uint32_t af[4][4];
#pragma unroll
            for (int mt = 0; mt < 4; mt++) {
                const float* pa = Ab + (mb + mt * 16 + (lane >> 2)) * GSTR + kk + (lane & 3);
                af[mt][0] = fbits(pa[0]);
                af[mt][1] = fbits(pa[8 * GSTR]);
                af[mt][2] = fbits(pa[4]);
                af[mt][3] = fbits(pa[8 * GSTR + 4]);
            }
#pragma unroll
            for (int nt = 0; nt < 4; nt++) {
                const float* pb = Bb + (nb + nt * 8 + (lane >> 2)) * GSTR + kk + (lane & 3);
                uint32_t b0 = fbits(pb[0]), b1 = fbits(pb[4]);
#pragma unroll
                for (int mt = 0; mt < 4; mt++)
                    mma_tf32(acc[mt][nt], af[mt][0], af[mt][1], af[mt][2], af[mt][3], b0, b1);
            }
        }
        // no trailing sync: next iteration's wait+sync protects buffer reuse
    }

    // epilogue
#pragma unroll
    for (int mt = 0; mt < 4; mt++) {
        const int row0 = m0 + mb + mt * 16 + (lane >> 2);
#pragma unroll
        for (int nt = 0; nt < 4; nt++) {
            const int col = n0 + nb + nt * 8 + (lane & 3) * 2;
            float bv0 = __ldg(bias + col), bv1 = __ldg(bias + col + 1);
            float2 o0 = { acc[mt][nt][0] + bv0, acc[mt][nt][1] + bv1 };
            float2 o1 = { acc[mt][nt][2] + bv0, acc[mt][nt][3] + bv1 };
            *(float2*)(C + (size_t)row0 * N + col)       = o0;
            *(float2*)(C + (size_t)(row0 + 8) * N + col) = o1;
        }
    }
}

// ---------------------------------------------------------------------------
// Flash attention, tf32 mma.sync, causal, register-prefetched K/V.
// CTA = 64 q-rows x (head, batch); 128 threads = 4 warps, warp owns 16 rows.
// ---------------------------------------------------------------------------
#define FSTR 68
#define VSTR 72
#define OFF_Q 0
#define OFF_K (64 * FSTR)
#define OFF_V (2 * 64 * FSTR)
#define OFF_P (2 * 64 * FSTR + 64 * VSTR)
#define FLASH_SMEM ((3 * 64 * FSTR + 64 * VSTR) * 4)   // 70656 B

__global__ __launch_bounds__(128, 3)
void flash_mma_kernel(const float* __restrict__ qkv, float* __restrict__ y)
{
    extern __shared__ float smf[];
    float* Qs = smf + OFF_Q;
    float* Ks = smf + OFF_K;
    float* Vs = smf + OFF_V;
    float* Ps = smf + OFF_P;

    const int tid = threadIdx.x;
    const int lane = tid & 31, wid = tid >> 5;
    const int qt = blockIdx.x;
    const int h  = blockIdx.y;
    const int b  = blockIdx.z;
    const int q0 = qt * 64;

    const float* qb = qkv + ((size_t)(b * SEQ + q0)) * C3 + h * HD;
    const float* kb = qkv + ((size_t)(b * SEQ)) * C3 + CH + h * HD;
    const float* vb = kb + CH;

    // Per-thread gmem slice coordinates (8 float4 each for K and V)
    int prow[8], pc4[8];
#pragma unroll
    for (int p = 0; p < 8; p++) {
        int i = tid + p * 128;
        prow[p] = i >> 4;
        pc4[p] = (i & 15) * 4;
    }

    // Q: scale + tf32 round into smem
    const float scale = 0.125f;
#pragma unroll
    for (int p = 0; p < 8; p++) {
        float4 v = *(const float4*)(qb + (size_t)prow[p] * C3 + pc4[p]);
        float4 o;
        o.x = to_tf32(v.x * scale); o.y = to_tf32(v.y * scale);
        o.z = to_tf32(v.z * scale); o.w = to_tf32(v.w * scale);
        *(float4*)&Qs[prow[p] * FSTR + pc4[p]] = o;
    }

    // prefetch K/V tile 0 into registers
    float4 kreg[8], vreg[8];
#pragma unroll
    for (int p = 0; p < 8; p++) {
        size_t g = (size_t)prow[p] * C3 + pc4[p];
        kreg[p] = *(const float4*)(kb + g);
        vreg[p] = *(const float4*)(vb + g);
    }

    float m0r = -1e30f, m1r = -1e30f, l0 = 0.f, l1 = 0.f;
    float oacc[8][4];
#pragma unroll
    for (int nt = 0; nt < 8; nt++)
#pragma unroll
        for (int r = 0; r < 4; r++) oacc[nt][r] = 0.f;

    const int qrow = 16 * wid + (lane >> 2);    // local q row (first half)

    for (int kt = 0; kt <= qt; kt++) {
        // store prefetched K/V (tf32-rounded) to smem
#pragma unroll
        for (int p = 0; p < 8; p++) {
            float4 ko, vo;
            ko.x = to_tf32(kreg[p].x); ko.y = to_tf32(kreg[p].y);
            ko.z = to_tf32(kreg[p].z); ko.w = to_tf32(kreg[p].w);
            vo.x = to_tf32(vreg[p].x); vo.y = to_tf32(vreg[p].y);
            vo.z = to_tf32(vreg[p].z); vo.w = to_tf32(vreg[p].w);
            *(float4*)&Ks[prow[p] * FSTR + pc4[p]] = ko;
            *(float4*)&Vs[prow[p] * VSTR + pc4[p]] = vo;
        }
        __syncthreads();

        // issue next tile's loads — latency hides under S/softmax/PV
        if (kt + 1 <= qt) {
#pragma unroll
            for (int p = 0; p < 8; p++) {
                size_t g = (size_t)((kt + 1) * 64 + prow[p]) * C3 + pc4[p];
                kreg[p] = *(const float4*)(kb + g);
                vreg[p] = *(const float4*)(vb + g);
            }
        }

        // S = Q @ K^T   (warp: 16 x 64)
        float sacc[8][4];
#pragma unroll
        for (int nt = 0; nt < 8; nt++)
#pragma unroll
            for (int r = 0; r < 4; r++) sacc[nt][r] = 0.f;

#pragma unroll
        for (int k = 0; k < 8; k++) {
            const int kk = k * 8;
            const float* pa = &Qs[qrow * FSTR + kk + (lane & 3)];
            uint32_t a0 = fbits(pa[0]), a1 = fbits(pa[8 * FSTR]);
            uint32_t a2 = fbits(pa[4]), a3 = fbits(pa[8 * FSTR + 4]);
#pragma unroll
            for (int nt = 0; nt < 8; nt++) {
                const float* pb = &Ks[(nt * 8 + (lane >> 2)) * FSTR + kk + (lane & 3)];
                mma_tf32(sacc[nt], a0, a1, a2, a3, fbits(pb[0]), fbits(pb[4]));
            }
        }

        // causal mask on diagonal tile
        if (kt == qt) {
#pragma unroll
            for (int nt = 0; nt < 8; nt++) {
                int c0 = nt * 8 + (lane & 3) * 2;
                if (c0     > qrow)     sacc[nt][0] = -1e30f;
                if (c0 + 1 > qrow)     sacc[nt][1] = -1e30f;
                if (c0     > qrow + 8) sacc[nt][2] = -1e30f;
                if (c0 + 1 > qrow + 8) sacc[nt][3] = -1e30f;
            }
        }

        // online softmax (two row-halves per thread)
        float mx0 = -1e30f, mx1 = -1e30f;
#pragma unroll
        for (int nt = 0; nt < 8; nt++) {
            mx0 = fmaxf(mx0, fmaxf(sacc[nt][0], sacc[nt][1]));
            mx1 = fmaxf(mx1, fmaxf(sacc[nt][2], sacc[nt][3]));
        }
        mx0 = fmaxf(mx0, __shfl_xor_sync(0xffffffffu, mx0, 1));
        mx0 = fmaxf(mx0, __shfl_xor_sync(0xffffffffu, mx0, 2));
        mx1 = fmaxf(mx1, __shfl_xor_sync(0xffffffffu, mx1, 1));
        mx1 = fmaxf(mx1, __shfl_xor_sync(0xffffffffu, mx1, 2));

        float mn0 = fmaxf(m0r, mx0), mn1 = fmaxf(m1r, mx1);
        float fac0 = __expf(m0r - mn0), fac1 = __expf(m1r - mn1);
        m0r = mn0; m1r = mn1;

        float rs0 = 0.f, rs1 = 0.f;
#pragma unroll
        for (int nt = 0; nt < 8; nt++) {
            sacc[nt][0] = __expf(sacc[nt][0] - mn0);
            sacc[nt][1] = __expf(sacc[nt][1] - mn0);
            sacc[nt][2] = __expf(sacc[nt][2] - mn1);
            sacc[nt][3] = __expf(sacc[nt][3] - mn1);
            rs0 += sacc[nt][0] + sacc[nt][1];
            rs1 += sacc[nt][2] + sacc[nt][3];
        }
        rs0 += __shfl_xor_sync(0xffffffffu, rs0, 1);
        rs0 += __shfl_xor_sync(0xffffffffu, rs0, 2);
        rs1 += __shfl_xor_sync(0xffffffffu, rs1, 1);
        rs1 += __shfl_xor_sync(0xffffffffu, rs1, 2);

        l0 = l0 * fac0 + rs0;
        l1 = l1 * fac1 + rs1;
#pragma unroll
        for (int nt = 0; nt < 8; nt++) {
            oacc[nt][0] *= fac0; oacc[nt][1] *= fac0;
            oacc[nt][2] *= fac1; oacc[nt][3] *= fac1;
        }

        // stage P (tf32-rounded) — warp-private rows
#pragma unroll
        for (int nt = 0; nt < 8; nt++) {
            int c = nt * 8 + (lane & 3) * 2;
            float2 p0 = { to_tf32(sacc[nt][0]), to_tf32(sacc[nt][1]) };
            float2 p1 = { to_tf32(sacc[nt][2]), to_tf32(sacc[nt][3]) };
            *(float2*)&Ps[qrow * FSTR + c]       = p0;
            *(float2*)&Ps[(qrow + 8) * FSTR + c] = p1;
        }
        __syncwarp();

        // O += P @ V   (warp: 16 x 64, k = 64 keys)
#pragma unroll
        for (int k = 0; k < 8; k++) {
            const int kk = k * 8;
            const float* pa = &Ps[qrow * FSTR + kk + (lane & 3)];
            uint32_t a0 = fbits(pa[0]), a1 = fbits(pa[8 * FSTR]);
            uint32_t a2 = fbits(pa[4]), a3 = fbits(pa[8 * FSTR + 4]);
#pragma unroll
            for (int nt = 0; nt < 8; nt++) {
                uint32_t b0 = fbits(Vs[(kk +     (lane & 3)) * VSTR + nt * 8 + (lane >> 2)]);
                uint32_t b1 = fbits(Vs[(kk + 4 + (lane & 3)) * VSTR + nt * 8 + (lane >> 2)]);
                mma_tf32(oacc[nt], a0, a1, a2, a3, b0, b1);
            }
        }
        __syncthreads();   // before next K/V overwrite
    }

    // epilogue: divide by l, tf32-round (input to out-proj), store
    float inv0 = 1.f / l0, inv1 = 1.f / l1;
    int r0 = q0 + 16 * wid + (lane >> 2);
    float* y0 = y + ((size_t)(b * SEQ + r0)) * CH + h * HD;
    float* y1 = y0 + 8 * CH;
#pragma unroll
    for (int nt = 0; nt < 8; nt++) {
        int c = nt * 8 + (lane & 3) * 2;
        float2 o0 = { to_tf32(oacc[nt][0] * inv0), to_tf32(oacc[nt][1] * inv0) };
        float2 o1 = { to_tf32(oacc[nt][2] * inv1), to_tf32(oacc[nt][3] * inv1) };
        *(float2*)(y0 + c) = o0;
        *(float2*)(y1 + c) = o1;
    }
}

// ---------------------------------------------------------------------------
extern "C" void kernel_launch(void* const* d_in, const int* in_sizes, int n_in,
                              void* d_out, int out_size)
{
    const float* x     = (const float*)d_in[0];
    const float* w_qkv = (const float*)d_in[1];
    const float* b_qkv = (const float*)d_in[2];
    const float* w_out = (const float*)d_in[3];
    const float* b_out = (const float*)d_in[4];
    float* out = (float*)d_out;

    float* qkv; cudaGetSymbolAddress((void**)&qkv, g_qkv);
    float* y;   cudaGetSymbolAddress((void**)&y,   g_y);
    float* xr;  cudaGetSymbolAddress((void**)&xr,  g_xr);
    float* wtq; cudaGetSymbolAddress((void**)&wtq, g_wtq);
    float* wto; cudaGetSymbolAddress((void**)&wto, g_wto);

    static bool attr_set = false;
    if (!attr_set) {
        cudaFuncSetAttribute(gemm_mma_kernel,
                             cudaFuncAttributeMaxDynamicSharedMemorySize, G_SMEM);
        cudaFuncSetAttribute(flash_mma_kernel,
                             cudaFuncAttributeMaxDynamicSharedMemorySize, FLASH_SMEM);
        attr_set = true;
    }

    // 0) precondition operands to tf32
    round_tf32_kernel<<<(MROWS * CH) / (256 * 4), 256>>>(x, xr);
    {
        dim3 blk(32, 8);
        transpose_round_kernel<<<dim3(C3 / 32, CH / 32), blk>>>(w_qkv, wtq, CH, C3);
        transpose_round_kernel<<<dim3(CH / 32, CH / 32), blk>>>(w_out, wto, CH, CH);
    }
    // 1) QKV projection: [4096,1024] @ [1024,3072] + b
    {
        dim3 grid(C3 / 128, MROWS / 128);
        gemm_mma_kernel<<<grid, 256, G_SMEM>>>(MROWS, C3, CH, xr, wtq, b_qkv, qkv);
    }
    // 2) causal flash attention -> y (tf32-rounded)
    {
        dim3 grid(SEQ / 64, NH, BATCH);
        flash_mma_kernel<<<grid, 128, FLASH_SMEM>>>(qkv, y);
    }
    // 3) output projection: [4096,1024] @ [1024,1024] + b
    {
        dim3 grid(CH / 128, MROWS / 128);
        gemm_mma_kernel<<<grid, 256, G_SMEM>>>(MROWS, CH, CH, y, wto, b_out, out);
    }
}

// round 6
// speedup vs baseline: 4.0750x; 1.0531x over previous
#include <cuda_runtime.h>
#include <cuda_bf16.h>
#include <cstdint>
#include <math.h>

// Problem constants
#define BATCH 2
#define SEQ   2048
#define CH    1024
#define NH    16
#define HD    64
#define C3    (3*CH)        // 3072
#define MROWS (BATCH*SEQ)   // 4096

// Scratch (allocation-guard safe: __device__ globals)
__device__ float g_qkv[(size_t)BATCH * SEQ * C3];   // [B,T,3C] tf32-rounded
__device__ float g_y  [(size_t)BATCH * SEQ * CH];   // [B,T,C]  tf32-rounded
__device__ float g_xr [(size_t)BATCH * SEQ * CH];   // x, tf32-rounded
__device__ float g_wtq[(size_t)C3 * CH];            // w_qkv^T, tf32-rounded
__device__ float g_wto[(size_t)CH * CH];            // w_out^T, tf32-rounded

// ---------------------------------------------------------------------------
// Helpers
// ---------------------------------------------------------------------------
__device__ __forceinline__ float to_tf32(float x) {
    float r; asm("cvt.rna.tf32.f32 %0, %1;" : "=f"(r) : "f"(x)); return r;
}
__device__ __forceinline__ uint32_t fbits(float x) { return __float_as_uint(x); }

__device__ __forceinline__ uint32_t smem_u32(const void* p) {
    uint32_t a;
    asm("{ .reg .u64 t; cvta.to.shared.u64 t, %1; cvt.u32.u64 %0, t; }" : "=r"(a) : "l"(p));
    return a;
}
__device__ __forceinline__ void cp16(uint32_t s, const void* g) {
    asm volatile("cp.async.cg.shared.global [%0], [%1], 16;" :: "r"(s), "l"(g));
}

// m16n8k8 tf32 MMA, D += A*B
__device__ __forceinline__ void mma_tf32(float* d,
                                         uint32_t a0, uint32_t a1, uint32_t a2, uint32_t a3,
                                         uint32_t b0, uint32_t b1) {
    asm volatile(
        "mma.sync.aligned.m16n8k8.row.col.f32.tf32.tf32.f32 "
        "{%0,%1,%2,%3}, {%4,%5,%6,%7}, {%8,%9}, {%0,%1,%2,%3};"
        : "+f"(d[0]), "+f"(d[1]), "+f"(d[2]), "+f"(d[3])
        : "r"(a0), "r"(a1), "r"(a2), "r"(a3), "r"(b0), "r"(b1));
}

// ---------------------------------------------------------------------------
// Elementwise tf32 round (for x)
// ---------------------------------------------------------------------------
__global__ __launch_bounds__(256)
void round_tf32_kernel(const float* __restrict__ in, float* __restrict__ out)
{
    int i = (blockIdx.x * 256 + threadIdx.x) * 4;
    float4 v = *(const float4*)(in + i);
    v.x = to_tf32(v.x); v.y = to_tf32(v.y); v.z = to_tf32(v.z); v.w = to_tf32(v.w);
    *(float4*)(out + i) = v;
}

// ---------------------------------------------------------------------------
// Transpose + tf32-round: out[c][r] = tf32(in[r][c]), in is [R,C]
// ---------------------------------------------------------------------------
__global__ __launch_bounds__(256, 8)
void transpose_round_kernel(const float* __restrict__ in, float* __restrict__ out, int R, int C)
{
    __shared__ float t[32][33];
    int tx = threadIdx.x, ty = threadIdx.y;     // 32 x 8
    int c0 = blockIdx.x * 32, r0 = blockIdx.y * 32;
#pragma unroll
    for (int k = 0; k < 4; k++)
        t[ty + 8 * k][tx] = in[(size_t)(r0 + ty + 8 * k) * C + c0 + tx];
    __syncthreads();
#pragma unroll
    for (int k = 0; k < 4; k++)
        out[(size_t)(c0 + ty + 8 * k) * R + r0 + tx] = to_tf32(t[tx][ty + 8 * k]);
}

// ---------------------------------------------------------------------------
// TF32 mma.sync GEMM: C[M,N] = A[M,K] @ Bt[N,K]^T + bias[N]
// CTA 128x128, 4 warps (warp tile 64x64), KC=32, 3-stage cp.async.
// smem stride 36 floats -> conflict-free fragment quads.
// RND: round output to tf32 (for qkv feeding attention).
// ---------------------------------------------------------------------------
#define GKC 32
#define GSTR 36
#define GTILE (128 * GSTR)                   // floats per buffer (18432 B)
#define GSTAGES 3
#define G_SMEM (2 * GSTAGES * GTILE * 4)     // 110592 B

template<bool RND>
__global__ __launch_bounds__(128, 2)
void gemm_mma_kernel(int M, int N, int K,
                     const float* __restrict__ A,
                     const float* __restrict__ Bt,
                     const float* __restrict__ bias,
                     float* __restrict__ C)
{
    extern __shared__ float smg[];
    const uint32_t smem_base = smem_u32(smg);

    const int tid = threadIdx.x;
    const int lane = tid & 31, wid = tid >> 5;   // 4 warps
    const int n0 = blockIdx.x * 128;
    const int m0 = blockIdx.y * 128;
    const int mb = (wid & 1) * 64;
    const int nb = (wid >> 1) * 64;

    float acc[4][8][4];
#pragma unroll
    for (int mt = 0; mt < 4; mt++)
#pragma unroll
        for (int nt = 0; nt < 8; nt++)
#pragma unroll
            for (int r = 0; r < 4; r++) acc[mt][nt][r] = 0.f;

    const int lr = tid >> 3;            // 0..15
    const int lc4 = (tid & 7) * 4;      // 0..28

    const int nch = K / GKC;

    auto issue = [&](int buf, int kb) {
        uint32_t a_s = smem_base + (uint32_t)buf * GTILE * 4;
        uint32_t b_s = smem_base + (uint32_t)(GSTAGES + buf) * GTILE * 4;
#pragma unroll
        for (int p = 0; p < 8; p++) {
            int r = lr + p * 16;
            cp16(a_s + (uint32_t)(r * GSTR + lc4) * 4, A  + (size_t)(m0 + r) * K + kb + lc4);
            cp16(b_s + (uint32_t)(r * GSTR + lc4) * 4, Bt + (size_t)(n0 + r) * K + kb + lc4);
        }
        asm volatile("cp.async.commit_group;");
    };

    issue(0, 0);
    if (nch > 1) issue(1, GKC);

    for (int c = 0; c < nch; c++) {
        if (c + 1 < nch) asm volatile("cp.async.wait_group 1;");
        else             asm volatile("cp.async.wait_group 0;");
        __syncthreads();
        if (c + 2 < nch) issue((c + 2) % GSTAGES, (c + 2) * GKC);

        const float* Ab = smg + (c % GSTAGES) * GTILE;
        const float* Bb = smg + (GSTAGES + (c % GSTAGES)) * GTILE;
#pragma unroll
        for (int k = 0; k < 4; k++) {
            const int kk = k * 8;
            uint32_t af[4][4];
#pragma unroll
            for (int mt = 0; mt < 4; mt++) {
                const float* pa = Ab + (mb + mt * 16 + (lane >> 2)) * GSTR + kk + (lane & 3);
                af[mt][0] = fbits(pa[0]);
                af[mt][1] = fbits(pa[8 * GSTR]);
                af[mt][2] = fbits(pa[4]);
                af[mt][3] = fbits(pa[8 * GSTR + 4]);
            }
#pragma unroll
            for (int nt = 0; nt < 8; nt++) {
                const float* pb = Bb + (nb + nt * 8 + (lane >> 2)) * GSTR + kk + (lane & 3);
                uint32_t b0 = fbits(pb[0]), b1 = fbits(pb[4]);
#pragma unroll
                for (int mt = 0; mt < 4; mt++)
                    mma_tf32(acc[mt][nt], af[mt][0], af[mt][1], af[mt][2], af[mt][3], b0, b1);
            }
        }
    }

    // epilogue
#pragma unroll
    for (int mt = 0; mt < 4; mt++) {
        const int row0 = m0 + mb + mt * 16 + (lane >> 2);
#pragma unroll
        for (int nt = 0; nt < 8; nt++) {
            const int col = n0 + nb + nt * 8 + (lane & 3) * 2;
            float bv0 = __ldg(bias + col), bv1 = __ldg(bias + col + 1);
            float2 o0 = { acc[mt][nt][0] + bv0, acc[mt][nt][1] + bv1 };
            float2 o1 = { acc[mt][nt][2] + bv0, acc[mt][nt][3] + bv1 };
            if (RND) {
                o0.x = to_tf32(o0.x); o0.y = to_tf32(o0.y);
                o1.x = to_tf32(o1.x); o1.y = to_tf32(o1.y);
            }
            *(float2*)(C + (size_t)row0 * N + col)       = o0;
            *(float2*)(C + (size_t)(row0 + 8) * N + col) = o1;
        }
    }
}

// ---------------------------------------------------------------------------
// Flash attention, tf32 mma.sync, causal.
// CTA = 128 q-rows x (head, batch); 256 threads = 8 warps, warp owns 16 rows.
// qkv is pre-rounded to tf32 -> K/V/Q copied raw via cp.async (double-buffered
// K/V). Scale 1/8 applied to S post-MMA (exact, power of two).
// ---------------------------------------------------------------------------
#define ASTR 68
#define AVSTR 72
#define A_OFF_Q 0
#define A_OFF_K0 8704
#define A_OFF_K1 13056
#define A_OFF_V0 17408
#define A_OFF_V1 22016
#define A_OFF_P  26624
#define ATT_SMEM (35328 * 4)   // 141312 B

__global__ __launch_bounds__(256, 1)
void flash_mma_kernel(const float* __restrict__ qkv, float* __restrict__ y)
{
    extern __shared__ float smf[];
    const uint32_t smem_base = smem_u32(smf);

    const int tid = threadIdx.x;
    const int lane = tid & 31, wid = tid >> 5;       // 8 warps
    const int qt = (int)gridDim.x - 1 - (int)blockIdx.x;  // big CTAs first
    const int h  = blockIdx.y;
    const int b  = blockIdx.z;
    const int q0 = qt * 128;

    const float* qb = qkv + ((size_t)(b * SEQ + q0)) * C3 + h * HD;
    const float* kb = qkv + ((size_t)(b * SEQ)) * C3 + CH + h * HD;
    const float* vb = kb + CH;

    const int kofs[2] = { A_OFF_K0, A_OFF_K1 };
    const int vofs[2] = { A_OFF_V0, A_OFF_V1 };

    auto issue_kv = [&](int buf, int kt) {
#pragma unroll
        for (int p = 0; p < 4; p++) {
            int idx = tid + p * 256;
            int row = idx >> 4, c4 = (idx & 15) * 4;
            size_t g = (size_t)(kt * 64 + row) * C3 + c4;
            cp16(smem_base + (uint32_t)(kofs[buf] + row * ASTR  + c4) * 4, kb + g);
            cp16(smem_base + (uint32_t)(vofs[buf] + row * AVSTR + c4) * 4, vb + g);
        }
        asm volatile("cp.async.commit_group;");
    };

    // prologue: Q (128x64) + K/V tile 0, one group
#pragma unroll
    for (int p = 0; p < 8; p++) {
        int idx = tid + p * 256;
        int row = idx >> 4, c4 = (idx & 15) * 4;
        cp16(smem_base + (uint32_t)(A_OFF_Q + row * ASTR + c4) * 4,
             qb + (size_t)row * C3 + c4);
    }
    issue_kv(0, 0);

    float m0r = -1e30f, m1r = -1e30f, l0 = 0.f, l1 = 0.f;
    float oacc[8][4];
#pragma unroll
    for (int nt = 0; nt < 8; nt++)
#pragma unroll
        for (int r = 0; r < 4; r++) oacc[nt][r] = 0.f;

    const int qrow = 16 * wid + (lane >> 2);     // local q row (first half)
    const int rg0 = q0 + qrow, rg1 = rg0 + 8;    // global rows
    const float* Qs = smf + A_OFF_Q;
    float* Ps = smf + A_OFF_P;

    const int ktmax = 2 * qt + 2;
    for (int kt = 0; kt < ktmax; kt++) {
        asm volatile("cp.async.wait_group 0;");
        __syncthreads();      // tile kt ready; all warps done with tile kt-1
        if (kt + 1 < ktmax) issue_kv((kt + 1) & 1, kt + 1);

        const float* Ks = smf + kofs[kt & 1];
        const float* Vs = smf + vofs[kt & 1];

        // S = Q @ K^T  (warp: 16 x 64)
        float sacc[8][4];
#pragma unroll
        for (int nt = 0; nt < 8; nt++)
#pragma unroll
            for (int r = 0; r < 4; r++) sacc[nt][r] = 0.f;

#pragma unroll
        for (int k = 0; k < 8; k++) {
            const int kk = k * 8;
            const float* pa = &Qs[qrow * ASTR + kk + (lane & 3)];
            uint32_t a0 = fbits(pa[0]), a1 = fbits(pa[8 * ASTR]);
            uint32_t a2 = fbits(pa[4]), a3 = fbits(pa[8 * ASTR + 4]);
#pragma unroll
            for (int nt = 0; nt < 8; nt++) {
                const float* pb = &Ks[(nt * 8 + (lane >> 2)) * ASTR + kk + (lane & 3)];
                mma_tf32(sacc[nt], a0, a1, a2, a3, fbits(pb[0]), fbits(pb[4]));
            }
        }

        // scale (exact) + causal mask
        const float scale = 0.125f;
#pragma unroll
        for (int nt = 0; nt < 8; nt++)
#pragma unroll
            for (int r = 0; r < 4; r++) sacc[nt][r] *= scale;

        if (kt >= 2 * qt) {
#pragma unroll
            for (int nt = 0; nt < 8; nt++) {
                int cg = kt * 64 + nt * 8 + (lane & 3) * 2;
                if (cg     > rg0) sacc[nt][0] = -1e30f;
                if (cg + 1 > rg0) sacc[nt][1] = -1e30f;
                if (cg     > rg1) sacc[nt][2] = -1e30f;
                if (cg + 1 > rg1) sacc[nt][3] = -1e30f;
            }
        }

        // online softmax
        float mx0 = -1e30f, mx1 = -1e30f;
#pragma unroll
        for (int nt = 0; nt < 8; nt++) {
            mx0 = fmaxf(mx0, fmaxf(sacc[nt][0], sacc[nt][1]));
            mx1 = fmaxf(mx1, fmaxf(sacc[nt][2], sacc[nt][3]));
        }
        mx0 = fmaxf(mx0, __shfl_xor_sync(0xffffffffu, mx0, 1));
        mx0 = fmaxf(mx0, __shfl_xor_sync(0xffffffffu, mx0, 2));
        mx1 = fmaxf(mx1, __shfl_xor_sync(0xffffffffu, mx1, 1));
        mx1 = fmaxf(mx1, __shfl_xor_sync(0xffffffffu, mx1, 2));

        float mn0 = fmaxf(m0r, mx0), mn1 = fmaxf(m1r, mx1);
        float fac0 = __expf(m0r - mn0), fac1 = __expf(m1r - mn1);
        m0r = mn0; m1r = mn1;

        float rs0 = 0.f, rs1 = 0.f;
#pragma unroll
        for (int nt = 0; nt < 8; nt++) {
            sacc[nt][0] = __expf(sacc[nt][0] - mn0);
            sacc[nt][1] = __expf(sacc[nt][1] - mn0);
            sacc[nt][2] = __expf(sacc[nt][2] - mn1);
            sacc[nt][3] = __expf(sacc[nt][3] - mn1);
            rs0 += sacc[nt][0] + sacc[nt][1];
            rs1 += sacc[nt][2] + sacc[nt][3];
        }
        rs0 += __shfl_xor_sync(0xffffffffu, rs0, 1);
        rs0 += __shfl_xor_sync(0xffffffffu, rs0, 2);
        rs1 += __shfl_xor_sync(0xffffffffu, rs1, 1);
        rs1 += __shfl_xor_sync(0xffffffffu, rs1, 2);

        l0 = l0 * fac0 + rs0;
        l1 = l1 * fac1 + rs1;
#pragma unroll
        for (int nt = 0; nt < 8; nt++) {
            oacc[nt][0] *= fac0; oacc[nt][1] *= fac0;
            oacc[nt][2] *= fac1; oacc[nt][3] *= fac1;
        }

        // stage P (tf32-rounded) — warp-private rows
#pragma unroll
        for (int nt = 0; nt < 8; nt++) {
            int c = nt * 8 + (lane & 3) * 2;
            float2 p0 = { to_tf32(sacc[nt][0]), to_tf32(sacc[nt][1]) };
            float2 p1 = { to_tf32(sacc[nt][2]), to_tf32(sacc[nt][3]) };
            *(float2*)&Ps[qrow * ASTR + c]       = p0;
            *(float2*)&Ps[(qrow + 8) * ASTR + c] = p1;
        }
        __syncwarp();

        // O += P @ V
#pragma unroll
        for (int k = 0; k < 8; k++) {
            const int kk = k * 8;
            const float* pa = &Ps[qrow * ASTR + kk + (lane & 3)];
            uint32_t a0 = fbits(pa[0]), a1 = fbits(pa[8 * ASTR]);
            uint32_t a2 = fbits(pa[4]), a3 = fbits(pa[8 * ASTR + 4]);
#pragma unroll
            for (int nt = 0; nt < 8; nt++) {
                uint32_t b0 = fbits(Vs[(kk +     (lane & 3)) * AVSTR + nt * 8 + (lane >> 2)]);
                uint32_t b1 = fbits(Vs[(kk + 4 + (lane & 3)) * AVSTR + nt * 8 + (lane >> 2)]);
                mma_tf32(oacc[nt], a0, a1, a2, a3, b0, b1);
            }
        }
        // next iteration's wait+sync protects K/V buffer reuse
    }

    // epilogue: divide by l, tf32-round (input to out-proj), store
    float inv0 = 1.f / l0, inv1 = 1.f / l1;
    float* y0 = y + ((size_t)(b * SEQ + rg0)) * CH + h * HD;
    float* y1 = y0 + 8 * CH;
#pragma unroll
    for (int nt = 0; nt < 8; nt++) {
        int c = nt * 8 + (lane & 3) * 2;
        float2 o0 = { to_tf32(oacc[nt][0] * inv0), to_tf32(oacc[nt][1] * inv0) };
        float2 o1 = { to_tf32(oacc[nt][2] * inv1), to_tf32(oacc[nt][3] * inv1) };
        *(float2*)(y0 + c) = o0;
        *(float2*)(y1 + c) = o1;
    }
}

// ---------------------------------------------------------------------------
extern "C" void kernel_launch(void* const* d_in, const int* in_sizes, int n_in,
                              void* d_out, int out_size)
{
    const float* x     = (const float*)d_in[0];
    const float* w_qkv = (const float*)d_in[1];
    const float* b_qkv = (const float*)d_in[2];
    const float* w_out = (const float*)d_in[3];
    const float* b_out = (const float*)d_in[4];
    float* out = (float*)d_out;

    float* qkv; cudaGetSymbolAddress((void**)&qkv, g_qkv);
    float* y;   cudaGetSymbolAddress((void**)&y,   g_y);
    float* xr;  cudaGetSymbolAddress((void**)&xr,  g_xr);
    float* wtq; cudaGetSymbolAddress((void**)&wtq, g_wtq);
    float* wto; cudaGetSymbolAddress((void**)&wto, g_wto);

    static bool attr_set = false;
    if (!attr_set) {
        cudaFuncSetAttribute(gemm_mma_kernel<true>,
                             cudaFuncAttributeMaxDynamicSharedMemorySize, G_SMEM);
        cudaFuncSetAttribute(gemm_mma_kernel<false>,
                             cudaFuncAttributeMaxDynamicSharedMemorySize, G_SMEM);
        cudaFuncSetAttribute(flash_mma_kernel,
                             cudaFuncAttributeMaxDynamicSharedMemorySize, ATT_SMEM);
        attr_set = true;
    }

    // 0) precondition operands to tf32
    round_tf32_kernel<<<(MROWS * CH) / (256 * 4), 256>>>(x, xr);
    {
        dim3 blk(32, 8);
        transpose_round_kernel<<<dim3(C3 / 32, CH / 32), blk>>>(w_qkv, wtq, CH, C3);
        transpose_round_kernel<<<dim3(CH / 32, CH / 32), blk>>>(w_out, wto, CH, CH);
    }
    // 1) QKV projection (output tf32-rounded for attention)
    {
        dim3 grid(C3 / 128, MROWS / 128);
        gemm_mma_kernel<true><<<grid, 128, G_SMEM>>>(MROWS, C3, CH, xr, wtq, b_qkv, qkv);
    }
    // 2) causal flash attention -> y (tf32-rounded)
    {
        dim3 grid(SEQ / 128, NH, BATCH);
        flash_mma_kernel<<<grid, 256, ATT_SMEM>>>(qkv, y);
    }
    // 3) output projection (fp32 output)
    {
        dim3 grid(CH / 128, MROWS / 128);
        gemm_mma_kernel<false><<<grid, 128, G_SMEM>>>(MROWS, CH, CH, y, wto, b_out, out);
    }
}